// round 9
// baseline (speedup 1.0000x reference)
#include <cuda_runtime.h>
#include <cuda_bf16.h>
#include <cstdint>

#define HW   256
#define HW2  65536
#define MAX_BS 128

// Scratch (__device__ globals, zero at module load — no allocations).
// g_table is restored to all-zero by gather_kernel (read-then-clear) so no
// memset node is ever needed. g_flag is a plain deterministic store each call.
__device__ int      g_table[MAX_BS * HW2];        // winner p per cell, 0 = empty (aliases p=0, same decode)
__device__ unsigned g_bits[MAX_BS * (HW2 / 32)];  // seg>0.5 bitmask
__device__ int      g_flag[MAX_BS];               // 1 if any valid px (written by fixup)

// ---------------------------------------------------------------------------
// K1: pure scatter, 8 px/thread. Reads seg+grid, emits bitmask,
//     RED.MAX for VALID px only. 32 blocks/batch (256 thr * 8 px = 2048).
// ---------------------------------------------------------------------------
__global__ void __launch_bounds__(256)
scatter_kernel(const float* __restrict__ grid, const float* __restrict__ seg) {
    int blk = blockIdx.x;
    int b   = blk >> 5;                    // 32 blocks per batch
    int sub = blk & 31;
    int tid = threadIdx.x;
    int p   = (sub << 11) + (tid << 3);    // in-batch pixel index (8/thread)

    const float* segb = seg + (size_t)b * HW2;
    float4 sa = __ldcs(reinterpret_cast<const float4*>(segb + p));
    float4 sb = __ldcs(reinterpret_cast<const float4*>(segb + p + 4));
    bool v[8] = {sa.x > 0.5f, sa.y > 0.5f, sa.z > 0.5f, sa.w > 0.5f,
                 sb.x > 0.5f, sb.y > 0.5f, sb.z > 0.5f, sb.w > 0.5f};

    // bitmask word (32 px = 4 threads * 8 bits), shuffle-OR assembly
    unsigned oct = 0;
    #pragma unroll
    for (int k = 0; k < 8; k++) oct |= ((unsigned)v[k]) << k;
    unsigned w = oct << ((tid & 3) << 3);
    w |= __shfl_xor_sync(0xffffffffu, w, 1);
    w |= __shfl_xor_sync(0xffffffffu, w, 2);
    if ((tid & 3) == 0) g_bits[(b << 11) + (p >> 5)] = w;

    const float* gxb = grid + (size_t)b * 2 * HW2;
    float4 xa = __ldcs(reinterpret_cast<const float4*>(gxb + p));
    float4 xb = __ldcs(reinterpret_cast<const float4*>(gxb + p + 4));
    float4 ya = __ldcs(reinterpret_cast<const float4*>(gxb + HW2 + p));
    float4 yb = __ldcs(reinterpret_cast<const float4*>(gxb + HW2 + p + 4));
    float gx[8] = {xa.x, xa.y, xa.z, xa.w, xb.x, xb.y, xb.z, xb.w};
    float gy[8] = {ya.x, ya.y, ya.z, ya.w, yb.x, yb.y, yb.z, yb.w};

    int* tb = g_table + b * HW2;
    #pragma unroll
    for (int k = 0; k < 8; k++) {
        if (v[k]) {
            int ix = (int)((gx[k] + 1.0f) * 0.5f * (float)HW);
            int iy = (int)((gy[k] + 1.0f) * 0.5f * (float)HW);
            ix = min(max(ix, 0), HW - 1);
            iy = min(max(iy, 0), HW - 1);
            atomicMax(&tb[iy * HW + ix], p + k);   // RED.MAX, no return
        }
    }
}

// ---------------------------------------------------------------------------
// K2: fixup, one block (256 thr) per batch. Scans seg top-down in 256-px
//     chunks; first chunk with an invalid pixel yields the global max-invalid
//     index. Non-empty -> plant its winner at the hot (128,128) cell;
//     empty -> full unmasked scatter for this batch (rare slow path).
// ---------------------------------------------------------------------------
__global__ void __launch_bounds__(256)
fixup_kernel(const float* __restrict__ grid, const float* __restrict__ seg) {
    int b = blockIdx.x;
    int tid = threadIdx.x;
    const float* segb = seg + (size_t)b * HW2;
    __shared__ int s_valid, s_minv;
    if (tid == 0) { s_valid = 0; s_minv = -1; }
    __syncthreads();

    for (int base = HW2 - 256; base >= 0; base -= 256) {
        int p = base + tid;
        float sv = segb[p];
        if (sv > 0.5f) s_valid = 1;
        else           atomicMax(&s_minv, p);
        __syncthreads();
        if (s_valid && s_minv >= 0) break;          // uniform decision
        __syncthreads();
    }

    int* tb = g_table + b * HW2;
    if (s_valid) {
        if (tid == 0 && s_minv >= 0)
            atomicMax(&tb[128 * HW + 128], s_minv); // dedup hot cell: 1 atomic
    } else {
        // empty batch: reference scatters ALL pixels unmasked
        const float* gxb = grid + (size_t)b * 2 * HW2;
        #pragma unroll 1
        for (int i = 0; i < 64; i++) {
            int p = ((i << 8) + tid) << 2;
            float4 gx4 = *reinterpret_cast<const float4*>(gxb + p);
            float4 gy4 = *reinterpret_cast<const float4*>(gxb + HW2 + p);
            float gx[4] = {gx4.x, gx4.y, gx4.z, gx4.w};
            float gy[4] = {gy4.x, gy4.y, gy4.z, gy4.w};
            #pragma unroll
            for (int k = 0; k < 4; k++) {
                int ix = (int)((gx[k] + 1.0f) * 0.5f * (float)HW);
                int iy = (int)((gy[k] + 1.0f) * 0.5f * (float)HW);
                ix = min(max(ix, 0), HW - 1);
                iy = min(max(iy, 0), HW - 1);
                atomicMax(&tb[iy * HW + ix], p + k);
            }
        }
    }
    if (tid == 0) g_flag[b] = s_valid;              // deterministic store
}

// ---------------------------------------------------------------------------
// K3: gather, 8 px/thread. Decode winners + nearest-sample + write 5 output
//     planes; re-zero table as it is read. ix = w&~1, iy = h&~1;
//     untouched cell (0) decodes to (0,0) which is exactly correct.
// ---------------------------------------------------------------------------
__global__ void __launch_bounds__(256)
gather_kernel(const float* __restrict__ conf, const float* __restrict__ depth,
              float* __restrict__ out, int bs) {
    int blk = blockIdx.x;
    int b   = blk >> 5;
    int sub = blk & 31;
    int tid = threadIdx.x;
    int p   = (sub << 11) + (tid << 3);

    bool emp = (__ldg(&g_flag[b]) == 0);
    int4* tp = reinterpret_cast<int4*>(g_table + b * HW2 + p);
    int4 ka = tp[0];
    int4 kb = tp[1];
    tp[0] = make_int4(0, 0, 0, 0);         // restore zero state for next call
    tp[1] = make_int4(0, 0, 0, 0);
    int s[8] = {ka.x, ka.y, ka.z, ka.w, kb.x, kb.y, kb.z, kb.w};

    const float* db = depth + (size_t)b * HW2;
    const float* cb = conf  + (size_t)b * HW2;
    const unsigned* bb = g_bits + (b << 11);

    // compute all cells first -> maximize outstanding random loads
    int cell[8];
    float mv[8];
    #pragma unroll
    for (int k = 0; k < 8; k++) {
        int ix = (s[k] & (HW - 1)) & ~1;
        int iy = ((s[k] >> 8) & (HW - 1)) & ~1;
        cell[k] = iy * HW + ix;
    }
    float dv[8], cv[8];
    #pragma unroll
    for (int k = 0; k < 8; k++) dv[k] = __ldg(db + cell[k]);
    #pragma unroll
    for (int k = 0; k < 8; k++) cv[k] = __ldg(cb + cell[k]);
    #pragma unroll
    for (int k = 0; k < 8; k++)
        mv[k] = (emp || ((__ldg(&bb[cell[k] >> 5]) >> (cell[k] & 31)) & 1u)) ? 1.0f : 0.0f;

    float ox[8], oy[8], od[8], oc[8];
    #pragma unroll
    for (int k = 0; k < 8; k++) {
        int ix = cell[k] & (HW - 1);
        int iy = cell[k] >> 8;
        ox[k] = ((float)ix * (1.0f / 280.0f)) * mv[k];
        oy[k] = ((float)iy * (1.0f / 280.0f)) * mv[k];
        od[k] = dv[k] * mv[k];
        oc[k] = cv[k];
    }

    size_t o0 = (size_t)b * 3 * HW2 + p;
    size_t oC = (size_t)bs * 3 * HW2 + (size_t)b * HW2 + p;
    size_t oM = (size_t)bs * 4 * HW2 + (size_t)b * HW2 + p;
    __stcs(reinterpret_cast<float4*>(out + o0),               make_float4(ox[0], ox[1], ox[2], ox[3]));
    __stcs(reinterpret_cast<float4*>(out + o0 + 4),           make_float4(ox[4], ox[5], ox[6], ox[7]));
    __stcs(reinterpret_cast<float4*>(out + o0 + HW2),         make_float4(oy[0], oy[1], oy[2], oy[3]));
    __stcs(reinterpret_cast<float4*>(out + o0 + HW2 + 4),     make_float4(oy[4], oy[5], oy[6], oy[7]));
    __stcs(reinterpret_cast<float4*>(out + o0 + 2 * HW2),     make_float4(od[0], od[1], od[2], od[3]));
    __stcs(reinterpret_cast<float4*>(out + o0 + 2 * HW2 + 4), make_float4(od[4], od[5], od[6], od[7]));
    __stcs(reinterpret_cast<float4*>(out + oC),               make_float4(oc[0], oc[1], oc[2], oc[3]));
    __stcs(reinterpret_cast<float4*>(out + oC + 4),           make_float4(oc[4], oc[5], oc[6], oc[7]));
    __stcs(reinterpret_cast<float4*>(out + oM),               make_float4(mv[0], mv[1], mv[2], mv[3]));
    __stcs(reinterpret_cast<float4*>(out + oM + 4),           make_float4(mv[4], mv[5], mv[6], mv[7]));
}

// ---------------------------------------------------------------------------
extern "C" void kernel_launch(void* const* d_in, const int* in_sizes, int n_in,
                              void* d_out, int out_size) {
    const float* grid  = (const float*)d_in[0];
    const float* seg   = (const float*)d_in[1];
    const float* conf  = (const float*)d_in[2];
    const float* depth = (const float*)d_in[3];
    float* out = (float*)d_out;

    int bs = in_sizes[1] / HW2;   // 128

    scatter_kernel<<<bs * 32, 256>>>(grid, seg);
    fixup_kernel<<<bs, 256>>>(grid, seg);
    gather_kernel<<<bs * 32, 256>>>(conf, depth, out, bs);
}

// round 10
// speedup vs baseline: 1.5784x; 1.5784x over previous
#include <cuda_runtime.h>
#include <cuda_bf16.h>
#include <cstdint>

#define HW   256
#define HW2  65536
#define MAX_BS 128
#define BPB  64            // blocks per batch (256 thr * 4 px = 1024 px/block)

// Scratch (__device__ globals, zero at module load — no allocations).
// g_table is restored to all-zero by gather_kernel (read-then-clear) so no
// memset node is ever needed. g_flag is a plain deterministic store each call.
__device__ int      g_table[MAX_BS * HW2];        // winner p per cell, 0 = empty (aliases p=0, same decode)
__device__ unsigned g_bits[MAX_BS * (HW2 / 32)];  // seg>0.5 bitmask
__device__ int      g_flag[MAX_BS];               // 1 if any valid px (written by fixup)
__device__ float2   g_dc[MAX_BS * (HW2 / 4)];     // packed {depth, conf} at (even iy, even ix), 16 MB

// ---------------------------------------------------------------------------
// K1: pure scatter, 4 px/thread (R8 shape). Reads seg+grid, emits bitmask,
//     RED.MAX for VALID px only.
// ---------------------------------------------------------------------------
__global__ void __launch_bounds__(256)
scatter_kernel(const float* __restrict__ grid, const float* __restrict__ seg) {
    int blk = blockIdx.x;
    int b   = blk >> 6;                    // / BPB
    int sub = blk & (BPB - 1);
    int tid = threadIdx.x;
    int p   = (sub << 10) + (tid << 2);    // in-batch pixel index (4/thread)

    const float* segb = seg + (size_t)b * HW2;
    float4 s4 = __ldcs(reinterpret_cast<const float4*>(segb + p));
    bool v[4] = {s4.x > 0.5f, s4.y > 0.5f, s4.z > 0.5f, s4.w > 0.5f};

    // bitmask word (32 px = 8 threads * 4 bits), shuffle-OR assembly
    unsigned nib = (unsigned)v[0] | ((unsigned)v[1] << 1) |
                   ((unsigned)v[2] << 2) | ((unsigned)v[3] << 3);
    unsigned w = nib << ((tid & 7) << 2);
    w |= __shfl_xor_sync(0xffffffffu, w, 1);
    w |= __shfl_xor_sync(0xffffffffu, w, 2);
    w |= __shfl_xor_sync(0xffffffffu, w, 4);
    if ((tid & 7) == 0) g_bits[(b << 11) + (p >> 5)] = w;

    const float* gxb = grid + (size_t)b * 2 * HW2;
    float4 gx4 = __ldcs(reinterpret_cast<const float4*>(gxb + p));
    float4 gy4 = __ldcs(reinterpret_cast<const float4*>(gxb + HW2 + p));
    float gx[4] = {gx4.x, gx4.y, gx4.z, gx4.w};
    float gy[4] = {gy4.x, gy4.y, gy4.z, gy4.w};

    int* tb = g_table + b * HW2;
    #pragma unroll
    for (int k = 0; k < 4; k++) {
        if (v[k]) {
            int ix = (int)((gx[k] + 1.0f) * 0.5f * (float)HW);
            int iy = (int)((gy[k] + 1.0f) * 0.5f * (float)HW);
            ix = min(max(ix, 0), HW - 1);
            iy = min(max(iy, 0), HW - 1);
            atomicMax(&tb[iy * HW + ix], p + k);   // RED.MAX, no return
        }
    }
}

// ---------------------------------------------------------------------------
// K2: fixup, one block (256 thr) per batch. Scans seg top-down in 256-px
//     chunks; first chunk with an invalid pixel yields the global max-invalid
//     index. Non-empty -> plant its winner at the hot (128,128) cell;
//     empty -> full unmasked scatter for this batch (rare slow path).
// ---------------------------------------------------------------------------
__global__ void __launch_bounds__(256)
fixup_kernel(const float* __restrict__ grid, const float* __restrict__ seg) {
    int b = blockIdx.x;
    int tid = threadIdx.x;
    const float* segb = seg + (size_t)b * HW2;
    __shared__ int s_valid, s_minv;
    if (tid == 0) { s_valid = 0; s_minv = -1; }
    __syncthreads();

    for (int base = HW2 - 256; base >= 0; base -= 256) {
        int p = base + tid;
        float sv = segb[p];
        if (sv > 0.5f) s_valid = 1;
        else           atomicMax(&s_minv, p);
        __syncthreads();
        if (s_valid && s_minv >= 0) break;          // uniform decision
        __syncthreads();
    }

    int* tb = g_table + b * HW2;
    if (s_valid) {
        if (tid == 0 && s_minv >= 0)
            atomicMax(&tb[128 * HW + 128], s_minv); // dedup hot cell: 1 atomic
    } else {
        // empty batch: reference scatters ALL pixels unmasked
        const float* gxb = grid + (size_t)b * 2 * HW2;
        #pragma unroll 1
        for (int i = 0; i < 64; i++) {
            int p = ((i << 8) + tid) << 2;
            float4 gx4 = *reinterpret_cast<const float4*>(gxb + p);
            float4 gy4 = *reinterpret_cast<const float4*>(gxb + HW2 + p);
            float gx[4] = {gx4.x, gx4.y, gx4.z, gx4.w};
            float gy[4] = {gy4.x, gy4.y, gy4.z, gy4.w};
            #pragma unroll
            for (int k = 0; k < 4; k++) {
                int ix = (int)((gx[k] + 1.0f) * 0.5f * (float)HW);
                int iy = (int)((gy[k] + 1.0f) * 0.5f * (float)HW);
                ix = min(max(ix, 0), HW - 1);
                iy = min(max(iy, 0), HW - 1);
                atomicMax(&tb[iy * HW + ix], p + k);
            }
        }
    }
    if (tid == 0) g_flag[b] = s_valid;              // deterministic store
}

// ---------------------------------------------------------------------------
// K2.5: pack {depth, conf} at (even iy, even ix) into g_dc (128x128/batch).
//       16 blocks/batch, 256 thr, 4 cells/thread.
// ---------------------------------------------------------------------------
__global__ void __launch_bounds__(256)
pack_kernel(const float* __restrict__ conf, const float* __restrict__ depth) {
    int blk = blockIdx.x;
    int b   = blk >> 4;
    int sub = blk & 15;
    int tid = threadIdx.x;
    int pc  = (sub << 10) + (tid << 2);    // packed cell index (4/thread)
    int iy2 = pc >> 7;
    int ix2 = pc & 127;

    size_t src = (size_t)b * HW2 + (iy2 << 1) * HW + (ix2 << 1);
    // 4 packed cells -> full ix = 2*ix2 .. 2*ix2+7 -> two float4 loads, even lanes
    float4 da = __ldcs(reinterpret_cast<const float4*>(depth + src));
    float4 db = __ldcs(reinterpret_cast<const float4*>(depth + src + 4));
    float4 ca = __ldcs(reinterpret_cast<const float4*>(conf  + src));
    float4 cb = __ldcs(reinterpret_cast<const float4*>(conf  + src + 4));

    float2* dst = g_dc + b * (HW2 / 4) + pc;
    dst[0] = make_float2(da.x, ca.x);
    dst[1] = make_float2(da.z, ca.z);
    dst[2] = make_float2(db.x, cb.x);
    dst[3] = make_float2(db.z, cb.z);
}

// ---------------------------------------------------------------------------
// K3: gather, 4 px/thread (R8 shape). Decode winners + nearest-sample via the
//     packed {d,c} table + write 5 output planes; re-zero winner table.
//     ix = w&~1, iy = h&~1; untouched cell (0) decodes to (0,0), correct.
// ---------------------------------------------------------------------------
__global__ void __launch_bounds__(256)
gather_kernel(float* __restrict__ out, int bs) {
    int blk = blockIdx.x;
    int b   = blk >> 6;
    int sub = blk & (BPB - 1);
    int tid = threadIdx.x;
    int p   = (sub << 10) + (tid << 2);

    bool emp = (__ldg(&g_flag[b]) == 0);
    int4* tp = reinterpret_cast<int4*>(g_table + b * HW2 + p);
    int4 k4 = *tp;
    *tp = make_int4(0, 0, 0, 0);           // restore zero state for next call
    int s[4] = {k4.x, k4.y, k4.z, k4.w};

    const float2* dcb = g_dc + b * (HW2 / 4);
    const unsigned* bb = g_bits + (b << 11);

    float4 ox, oy, od, oc, om;
    float *oxp = &ox.x, *oyp = &oy.x, *odp = &od.x, *ocp = &oc.x, *omp = &om.x;
    #pragma unroll
    for (int k = 0; k < 4; k++) {
        int ix = (s[k] & (HW - 1)) & ~1;
        int iy = ((s[k] >> 8) & (HW - 1)) & ~1;
        int cell = iy * HW + ix;
        int pc   = ((iy >> 1) << 7) | (ix >> 1);
        float2 dc = __ldg(dcb + pc);
        float m = (emp || ((__ldg(&bb[cell >> 5]) >> (cell & 31)) & 1u)) ? 1.0f : 0.0f;
        oxp[k] = ((float)ix * (1.0f / 280.0f)) * m;
        oyp[k] = ((float)iy * (1.0f / 280.0f)) * m;
        odp[k] = dc.x * m;
        ocp[k] = dc.y;
        omp[k] = m;
    }

    size_t o0 = (size_t)b * 3 * HW2 + p;
    __stcs(reinterpret_cast<float4*>(out + o0),           ox);
    __stcs(reinterpret_cast<float4*>(out + o0 + HW2),     oy);
    __stcs(reinterpret_cast<float4*>(out + o0 + 2 * HW2), od);
    __stcs(reinterpret_cast<float4*>(out + (size_t)bs * 3 * HW2 + (size_t)b * HW2 + p), oc);
    __stcs(reinterpret_cast<float4*>(out + (size_t)bs * 4 * HW2 + (size_t)b * HW2 + p), om);
}

// ---------------------------------------------------------------------------
extern "C" void kernel_launch(void* const* d_in, const int* in_sizes, int n_in,
                              void* d_out, int out_size) {
    const float* grid  = (const float*)d_in[0];
    const float* seg   = (const float*)d_in[1];
    const float* conf  = (const float*)d_in[2];
    const float* depth = (const float*)d_in[3];
    float* out = (float*)d_out;

    int bs = in_sizes[1] / HW2;   // 128

    scatter_kernel<<<bs * BPB, 256>>>(grid, seg);
    fixup_kernel<<<bs, 256>>>(grid, seg);
    pack_kernel<<<bs * 16, 256>>>(conf, depth);
    gather_kernel<<<bs * BPB, 256>>>(out, bs);
}

// round 11
// speedup vs baseline: 1.6046x; 1.0166x over previous
#include <cuda_runtime.h>
#include <cuda_bf16.h>
#include <cstdint>

#define HW   256
#define HW2  65536
#define MAX_BS 128
#define BPB  64            // scatter blocks per batch (256 thr * 4 px = 1024 px/block)

// Scratch (__device__ globals, zero at module load — no allocations).
// g_table is restored to all-zero by gather_kernel (read-then-clear) so no
// memset node is ever needed. g_flag is a plain deterministic store each call.
__device__ int      g_table[MAX_BS * HW2];        // winner p per cell, 0 = empty (aliases p=0, same decode)
__device__ unsigned g_bits[MAX_BS * (HW2 / 32)];  // seg>0.5 bitmask
__device__ int      g_flag[MAX_BS];               // 1 if any valid px
__device__ float2   g_dc[MAX_BS * (HW2 / 4)];     // packed {depth, conf} at (even iy, even ix), 16 MB

// ---------------------------------------------------------------------------
// K1: merged producer. Role-dispatched blocks:
//   [0, bs)                      : fixup  (scan + hot-cell plant / empty path)
//   [bs, bs + bs*16)             : pack   ({depth,conf} -> g_dc)
//   [bs + bs*16, bs + bs*16+bs*64): scatter (seg+grid -> bits + RED.MAX table)
// All table writes are atomicMax -> order-independent; kernel boundary is the
// only barrier gather needs.
// ---------------------------------------------------------------------------
__global__ void __launch_bounds__(256)
produce_kernel(const float* __restrict__ grid, const float* __restrict__ seg,
               const float* __restrict__ conf, const float* __restrict__ depth,
               int bs) {
    int blk = blockIdx.x;
    int tid = threadIdx.x;

    if (blk < bs) {
        // ---------------- fixup role ----------------
        int b = blk;
        const float* segb = seg + (size_t)b * HW2;
        __shared__ int s_valid, s_minv;
        if (tid == 0) { s_valid = 0; s_minv = -1; }
        __syncthreads();

        for (int base = HW2 - 256; base >= 0; base -= 256) {
            int p = base + tid;
            float sv = segb[p];
            if (sv > 0.5f) s_valid = 1;
            else           atomicMax(&s_minv, p);
            __syncthreads();
            if (s_valid && s_minv >= 0) break;          // uniform decision
            __syncthreads();
        }

        int* tb = g_table + b * HW2;
        if (s_valid) {
            if (tid == 0 && s_minv >= 0)
                atomicMax(&tb[128 * HW + 128], s_minv); // dedup hot cell: 1 atomic
        } else {
            // empty batch: reference scatters ALL pixels unmasked (rare)
            const float* gxb = grid + (size_t)b * 2 * HW2;
            #pragma unroll 1
            for (int i = 0; i < 64; i++) {
                int p = ((i << 8) + tid) << 2;
                float4 gx4 = *reinterpret_cast<const float4*>(gxb + p);
                float4 gy4 = *reinterpret_cast<const float4*>(gxb + HW2 + p);
                float gx[4] = {gx4.x, gx4.y, gx4.z, gx4.w};
                float gy[4] = {gy4.x, gy4.y, gy4.z, gy4.w};
                #pragma unroll
                for (int k = 0; k < 4; k++) {
                    int ix = (int)((gx[k] + 1.0f) * 0.5f * (float)HW);
                    int iy = (int)((gy[k] + 1.0f) * 0.5f * (float)HW);
                    ix = min(max(ix, 0), HW - 1);
                    iy = min(max(iy, 0), HW - 1);
                    atomicMax(&tb[iy * HW + ix], p + k);
                }
            }
        }
        if (tid == 0) g_flag[b] = s_valid;              // deterministic store
        return;
    }

    blk -= bs;
    if (blk < bs * 16) {
        // ---------------- pack role ----------------
        int b   = blk >> 4;
        int sub = blk & 15;
        int pc  = (sub << 10) + (tid << 2);    // packed cell index (4/thread)
        int iy2 = pc >> 7;
        int ix2 = pc & 127;

        size_t src = (size_t)b * HW2 + (iy2 << 1) * HW + (ix2 << 1);
        float4 da = __ldcs(reinterpret_cast<const float4*>(depth + src));
        float4 db = __ldcs(reinterpret_cast<const float4*>(depth + src + 4));
        float4 ca = __ldcs(reinterpret_cast<const float4*>(conf  + src));
        float4 cb = __ldcs(reinterpret_cast<const float4*>(conf  + src + 4));

        float2* dst = g_dc + b * (HW2 / 4) + pc;
        dst[0] = make_float2(da.x, ca.x);
        dst[1] = make_float2(da.z, ca.z);
        dst[2] = make_float2(db.x, cb.x);
        dst[3] = make_float2(db.z, cb.z);
        return;
    }

    // ---------------- scatter role ----------------
    blk -= bs * 16;
    int b   = blk >> 6;                    // / BPB
    int sub = blk & (BPB - 1);
    int p   = (sub << 10) + (tid << 2);    // in-batch pixel index (4/thread)

    const float* segb = seg + (size_t)b * HW2;
    float4 s4 = __ldcs(reinterpret_cast<const float4*>(segb + p));
    bool v[4] = {s4.x > 0.5f, s4.y > 0.5f, s4.z > 0.5f, s4.w > 0.5f};

    // bitmask word (32 px = 8 threads * 4 bits), shuffle-OR assembly
    unsigned nib = (unsigned)v[0] | ((unsigned)v[1] << 1) |
                   ((unsigned)v[2] << 2) | ((unsigned)v[3] << 3);
    unsigned w = nib << ((tid & 7) << 2);
    w |= __shfl_xor_sync(0xffffffffu, w, 1);
    w |= __shfl_xor_sync(0xffffffffu, w, 2);
    w |= __shfl_xor_sync(0xffffffffu, w, 4);
    if ((tid & 7) == 0) g_bits[(b << 11) + (p >> 5)] = w;

    const float* gxb = grid + (size_t)b * 2 * HW2;
    float4 gx4 = __ldcs(reinterpret_cast<const float4*>(gxb + p));
    float4 gy4 = __ldcs(reinterpret_cast<const float4*>(gxb + HW2 + p));
    float gx[4] = {gx4.x, gx4.y, gx4.z, gx4.w};
    float gy[4] = {gy4.x, gy4.y, gy4.z, gy4.w};

    int* tb = g_table + b * HW2;
    #pragma unroll
    for (int k = 0; k < 4; k++) {
        if (v[k]) {
            int ix = (int)((gx[k] + 1.0f) * 0.5f * (float)HW);
            int iy = (int)((gy[k] + 1.0f) * 0.5f * (float)HW);
            ix = min(max(ix, 0), HW - 1);
            iy = min(max(iy, 0), HW - 1);
            atomicMax(&tb[iy * HW + ix], p + k);   // RED.MAX, no return
        }
    }
}

// ---------------------------------------------------------------------------
// K2: gather, 4 px/thread. Decode winners + nearest-sample via packed {d,c}
//     table + write 5 output planes; re-zero winner table as it is read.
//     ix = w&~1, iy = h&~1; untouched cell (0) decodes to (0,0), correct.
// ---------------------------------------------------------------------------
__global__ void __launch_bounds__(256)
gather_kernel(float* __restrict__ out, int bs) {
    int blk = blockIdx.x;
    int b   = blk >> 6;
    int sub = blk & (BPB - 1);
    int tid = threadIdx.x;
    int p   = (sub << 10) + (tid << 2);

    bool emp = (__ldg(&g_flag[b]) == 0);
    int4* tp = reinterpret_cast<int4*>(g_table + b * HW2 + p);
    int4 k4 = *tp;
    *tp = make_int4(0, 0, 0, 0);           // restore zero state for next call
    int s[4] = {k4.x, k4.y, k4.z, k4.w};

    const float2* dcb = g_dc + b * (HW2 / 4);
    const unsigned* bb = g_bits + (b << 11);

    float4 ox, oy, od, oc, om;
    float *oxp = &ox.x, *oyp = &oy.x, *odp = &od.x, *ocp = &oc.x, *omp = &om.x;
    #pragma unroll
    for (int k = 0; k < 4; k++) {
        int ix = (s[k] & (HW - 1)) & ~1;
        int iy = ((s[k] >> 8) & (HW - 1)) & ~1;
        int cell = iy * HW + ix;
        int pc   = ((iy >> 1) << 7) | (ix >> 1);
        float2 dc = __ldg(dcb + pc);
        float m = (emp || ((__ldg(&bb[cell >> 5]) >> (cell & 31)) & 1u)) ? 1.0f : 0.0f;
        oxp[k] = ((float)ix * (1.0f / 280.0f)) * m;
        oyp[k] = ((float)iy * (1.0f / 280.0f)) * m;
        odp[k] = dc.x * m;
        ocp[k] = dc.y;
        omp[k] = m;
    }

    size_t o0 = (size_t)b * 3 * HW2 + p;
    __stcs(reinterpret_cast<float4*>(out + o0),           ox);
    __stcs(reinterpret_cast<float4*>(out + o0 + HW2),     oy);
    __stcs(reinterpret_cast<float4*>(out + o0 + 2 * HW2), od);
    __stcs(reinterpret_cast<float4*>(out + (size_t)bs * 3 * HW2 + (size_t)b * HW2 + p), oc);
    __stcs(reinterpret_cast<float4*>(out + (size_t)bs * 4 * HW2 + (size_t)b * HW2 + p), om);
}

// ---------------------------------------------------------------------------
extern "C" void kernel_launch(void* const* d_in, const int* in_sizes, int n_in,
                              void* d_out, int out_size) {
    const float* grid  = (const float*)d_in[0];
    const float* seg   = (const float*)d_in[1];
    const float* conf  = (const float*)d_in[2];
    const float* depth = (const float*)d_in[3];
    float* out = (float*)d_out;

    int bs = in_sizes[1] / HW2;   // 128

    int nprod = bs + bs * 16 + bs * BPB;  // fixup + pack + scatter roles
    produce_kernel<<<nprod, 256>>>(grid, seg, conf, depth, bs);
    gather_kernel<<<bs * BPB, 256>>>(out, bs);
}